// round 12
// baseline (speedup 1.0000x reference)
#include <cuda_runtime.h>
#include <cuda_bf16.h>

// RetinaFace decode, N = 1e6 priors. Pair mapping (2 threads/prior, 256-bit
// ld/st with L2 hints) x 2 priors per thread via SPLIT-STRIDE (half-rows t and
// t+N; N even => same role both times => no extra divergence), doubling MLP.
//   role 0: loc(4) + {c0,c1,lm0x,lm0y}  -> box, conf, det rows 0-1
//   role 1: {lm1,lm2} + {lm3,lm4}       -> det rows 2-3
//
// Output layout (float32):
//   [0    , 4N )  boxes_m    (N,4)
//   [4N   , 5N )  conf_m     (N,)
//   [5N   , 6N )  pred_m     (N,)  == 0 always (2-class)
//   [6N   , 22N)  detections (1,N,16)
//   [22N  , 23N)  keep       (N,)

struct U64x4 { unsigned long long a, b, c, d; };

__device__ __forceinline__ U64x4 ld_evl256(const void* p) {
    U64x4 v;
    asm("ld.global.L2::evict_last.v4.b64 {%0,%1,%2,%3}, [%4];"
        : "=l"(v.a), "=l"(v.b), "=l"(v.c), "=l"(v.d) : "l"(p));
    return v;
}
__device__ __forceinline__ void st_evf256(void* p, U64x4 v) {
    asm volatile("st.global.L2::evict_first.v4.b64 [%0], {%1,%2,%3,%4};"
                 :: "l"(p), "l"(v.a), "l"(v.b), "l"(v.c), "l"(v.d) : "memory");
}
__device__ __forceinline__ float2 unpack(unsigned long long u) {
    float2 f;
    asm("mov.b64 {%0,%1}, %2;" : "=f"(f.x), "=f"(f.y) : "l"(u));
    return f;
}
__device__ __forceinline__ unsigned long long pack(float x, float y) {
    unsigned long long u;
    asm("mov.b64 %0, {%1,%2};" : "=l"(u) : "f"(x), "f"(y));
    return u;
}

__device__ __forceinline__ void process_half(
    int r, int q, U64x4 vin, float4 p, float diff,
    float v1, float sx, float sy, float th,
    float* __restrict__ out, size_t Ns, size_t half_slot)
{
    float2 f0 = unpack(vin.a);
    float2 f1 = unpack(vin.b);
    float2 f2 = unpack(vin.c);
    float2 f3 = unpack(vin.d);

    float conf = 1.0f / (1.0f + __expf(-fabsf(diff)));
    bool  keep = (diff > 0.0f) && (conf > th);
    float mf   = keep ? 1.0f : 0.0f;

    U64x4 det_half;
    if (r == 0) {
        float cx = p.x + f0.x * sx;
        float cy = p.y + f0.y * sy;
        float w  = p.z * __expf(f1.x * v1);
        float h  = p.w * __expf(f1.y * v1);
        float x0 = cx - 0.5f * w;
        float y0 = cy - 0.5f * h;
        float x1 = x0 + w;
        float y1 = y0 + h;
        float4 box = make_float4(x0 * mf, y0 * mf, x1 * mf, y1 * mf);
        float confm = conf * mf;
        det_half.a = pack(box.x, box.y);
        det_half.b = pack(box.z, box.w);
        det_half.c = pack(confm, 0.0f);
        det_half.d = pack((p.x + f3.x * sx) * mf, (p.y + f3.y * sy) * mf);

        reinterpret_cast<float4*>(out)[q] = box;     // boxes_m
        out[4 * Ns + q] = confm;                     // conf_m
    } else {
        det_half.a = pack((p.x + f0.x * sx) * mf, (p.y + f0.y * sy) * mf);
        det_half.b = pack((p.x + f1.x * sx) * mf, (p.y + f1.y * sy) * mf);
        det_half.c = pack((p.x + f2.x * sx) * mf, (p.y + f2.y * sy) * mf);
        det_half.d = pack((p.x + f3.x * sx) * mf, (p.y + f3.y * sy) * mf);

        out[5 * Ns + q]  = 0.0f;                     // pred_m (always 0)
        out[22 * Ns + q] = mf;                       // keep
    }
    st_evf256(out + 6 * Ns + 8 * half_slot, det_half);
}

__global__ __launch_bounds__(128) void retina_decode_kernel(
    const float* __restrict__ in,       // [N,16]
    const float4* __restrict__ priors,  // [N] float4
    const float* __restrict__ thr,
    const float* __restrict__ var,
    float* __restrict__ out,
    int N)                              // N must be even (N = 1e6)
{
    const int t = blockIdx.x * 128 + threadIdx.x;   // half-row index, [0, N)
    if (t >= N) return;
    const int r  = t & 1;                // role (same for both half-rows)
    const int q0 = t >> 1;               // first prior
    const int q1 = q0 + (N >> 1);        // second prior (half-row t + N)

    const float v0 = var[0];
    const float v1 = var[1];
    const float th = thr[0];

    // Front-batch all 4 independent loads (MLP = 4)
    U64x4 va = ld_evl256(in + (size_t)8 * t);
    U64x4 vb = ld_evl256(in + (size_t)8 * (t + N));
    float4 pa = priors[q0];
    float4 pb = priors[q1];

    // class scores live in role-0 lane's .c component: broadcast width-2
    float2 f2a = unpack(va.c);
    float2 f2b = unpack(vb.c);
    float diffa = __shfl_sync(0xffffffffu, f2a.y - f2a.x, 0, 2);
    float diffb = __shfl_sync(0xffffffffu, f2b.y - f2b.x, 0, 2);

    size_t Ns = (size_t)N;
    process_half(r, q0, va, pa, diffa, v1, v0 * pa.z, v0 * pa.w, th, out, Ns, (size_t)t);
    process_half(r, q1, vb, pb, diffb, v1, v0 * pb.z, v0 * pb.w, th, out, Ns, (size_t)t + N);
}

extern "C" void kernel_launch(void* const* d_in, const int* in_sizes, int n_in,
                              void* d_out, int out_size)
{
    const float*  in     = (const float*)d_in[0];
    const float*  thr    = (const float*)d_in[1];
    const float4* priors = (const float4*)d_in[2];
    const float*  var    = (const float*)d_in[3];
    float* out = (float*)d_out;

    int N = in_sizes[2] / 4;   // priors is [N,4]

    int threads = 128;
    int blocks  = (N + threads - 1) / threads;   // N threads, 2 half-rows each
    retina_decode_kernel<<<blocks, threads>>>(in, priors, thr, var, out, N);
}

// round 13
// speedup vs baseline: 1.0177x; 1.0177x over previous
#include <cuda_runtime.h>
#include <cuda_bf16.h>
#include <cstdint>

// RetinaFace decode, N = 1e6 priors. Pair mapping (2 threads/prior, 256-bit
// evict_last loads) + TMA bulk stores: each block (64 priors) stages all its
// output in SMEM and issues 5 cp.async.bulk shared->global copies, turning
// scattered STG wavefronts into contiguous 4KB/1KB DRAM bursts.
//
//   role 0: loc(4) + {c0,c1,lm0x,lm0y}  -> box, conf, det rows 0-1
//   role 1: {lm1,lm2} + {lm3,lm4}       -> det rows 2-3
//
// Output layout (float32):
//   [0    , 4N )  boxes_m    (N,4)
//   [4N   , 5N )  conf_m     (N,)
//   [5N   , 6N )  pred_m     (N,)  == 0 always (2-class)
//   [6N   , 22N)  detections (1,N,16)
//   [22N  , 23N)  keep       (N,)

struct U64x4 { unsigned long long a, b, c, d; };

__device__ __forceinline__ U64x4 ld_evl256(const void* p) {
    U64x4 v;
    asm("ld.global.L2::evict_last.v4.b64 {%0,%1,%2,%3}, [%4];"
        : "=l"(v.a), "=l"(v.b), "=l"(v.c), "=l"(v.d) : "l"(p));
    return v;
}
__device__ __forceinline__ void st_evf256(void* p, U64x4 v) {
    asm volatile("st.global.L2::evict_first.v4.b64 [%0], {%1,%2,%3,%4};"
                 :: "l"(p), "l"(v.a), "l"(v.b), "l"(v.c), "l"(v.d) : "memory");
}
__device__ __forceinline__ float2 unpack(unsigned long long u) {
    float2 f;
    asm("mov.b64 {%0,%1}, %2;" : "=f"(f.x), "=f"(f.y) : "l"(u));
    return f;
}
__device__ __forceinline__ unsigned long long pack(float x, float y) {
    unsigned long long u;
    asm("mov.b64 %0, {%1,%2};" : "=l"(u) : "f"(x), "f"(y));
    return u;
}
__device__ __forceinline__ void bulk_store(void* gdst, uint32_t ssrc, uint32_t bytes) {
    asm volatile("cp.async.bulk.global.shared::cta.bulk_group [%0], [%1], %2;"
                 :: "l"(gdst), "r"(ssrc), "r"(bytes) : "memory");
}

// SMEM layout (bytes): det 4096 | boxes 1024 | conf 256 | pred 256 | keep 256
#define SM_DET  0
#define SM_BOX  4096
#define SM_CONF 5120
#define SM_PRED 5376
#define SM_KEEP 5632
#define SM_TOT  5888

__global__ __launch_bounds__(128) void retina_decode_kernel(
    const float* __restrict__ in,       // [N,16]
    const float4* __restrict__ priors,  // [N] float4
    const float* __restrict__ thr,
    const float* __restrict__ var,
    float* __restrict__ out,
    int N)
{
    __shared__ __align__(16) unsigned char sm[SM_TOT];

    const int t   = threadIdx.x;
    const int blk = blockIdx.x;
    const int r   = t & 1;                 // role
    const int ql  = t >> 1;                // local prior 0..63
    const int q   = blk * 64 + ql;         // global prior
    const size_t half = (size_t)blk * 128 + t;   // global half-row index

    const bool active = (q < N);
    const bool full   = (blk * 64 + 64) <= N;

    const float v0 = var[0];
    const float v1 = var[1];
    const float th = thr[0];

    U64x4 vin = {0, 0, 0, 0};
    float4 p  = make_float4(0.f, 0.f, 1.f, 1.f);
    if (active) {
        vin = ld_evl256(in + 8 * half);
        p   = priors[q];
    }
    float2 f0 = unpack(vin.a);
    float2 f1 = unpack(vin.b);
    float2 f2 = unpack(vin.c);
    float2 f3 = unpack(vin.d);

    // class scores in role-0 lane's .c: broadcast width-2 (all lanes participate)
    float diff = __shfl_sync(0xffffffffu, f2.y - f2.x, 0, 2);
    float conf = 1.0f / (1.0f + __expf(-fabsf(diff)));
    bool  keep = (diff > 0.0f) && (conf > th);
    float mf   = keep ? 1.0f : 0.0f;

    float sx = v0 * p.z;
    float sy = v0 * p.w;

    size_t Ns = (size_t)N;
    U64x4 det_half;
    float4 box;
    float confm = conf * mf;

    if (r == 0) {
        float cx = p.x + f0.x * sx;
        float cy = p.y + f0.y * sy;
        float w  = p.z * __expf(f1.x * v1);
        float h  = p.w * __expf(f1.y * v1);
        float x0 = cx - 0.5f * w;
        float y0 = cy - 0.5f * h;
        float x1 = x0 + w;
        float y1 = y0 + h;
        box = make_float4(x0 * mf, y0 * mf, x1 * mf, y1 * mf);
        det_half.a = pack(box.x, box.y);
        det_half.b = pack(box.z, box.w);
        det_half.c = pack(confm, 0.0f);
        det_half.d = pack((p.x + f3.x * sx) * mf, (p.y + f3.y * sy) * mf);
    } else {
        det_half.a = pack((p.x + f0.x * sx) * mf, (p.y + f0.y * sy) * mf);
        det_half.b = pack((p.x + f1.x * sx) * mf, (p.y + f1.y * sy) * mf);
        det_half.c = pack((p.x + f2.x * sx) * mf, (p.y + f2.y * sy) * mf);
        det_half.d = pack((p.x + f3.x * sx) * mf, (p.y + f3.y * sy) * mf);
    }

    if (full) {
        // ---- stage all outputs in SMEM ----
        if (true) {
            ulonglong2* dp = reinterpret_cast<ulonglong2*>(sm + SM_DET + 32 * t);
            dp[0] = make_ulonglong2(det_half.a, det_half.b);
            dp[1] = make_ulonglong2(det_half.c, det_half.d);
            if (r == 0) {
                reinterpret_cast<float4*>(sm + SM_BOX)[ql] = box;
                reinterpret_cast<float*>(sm + SM_CONF)[ql] = confm;
            } else {
                reinterpret_cast<float*>(sm + SM_PRED)[ql] = 0.0f;
                reinterpret_cast<float*>(sm + SM_KEEP)[ql] = mf;
            }
        }
        __syncthreads();

        if (t == 0) {
            uint32_t sbase = (uint32_t)__cvta_generic_to_shared(sm);
            asm volatile("fence.proxy.async.shared::cta;" ::: "memory");
            bulk_store(out + 6 * Ns + (size_t)1024 * blk, sbase + SM_DET, 4096);
            bulk_store(out + (size_t)256 * blk,           sbase + SM_BOX, 1024);
            bulk_store(out + 4 * Ns + (size_t)64 * blk,   sbase + SM_CONF, 256);
            bulk_store(out + 5 * Ns + (size_t)64 * blk,   sbase + SM_PRED, 256);
            bulk_store(out + 22 * Ns + (size_t)64 * blk,  sbase + SM_KEEP, 256);
            asm volatile("cp.async.bulk.commit_group;" ::: "memory");
            asm volatile("cp.async.bulk.wait_group.read 0;" ::: "memory");
        }
    } else if (active) {
        // tail block (not hit for N=1e6): direct stores
        st_evf256(out + 6 * Ns + 8 * half, det_half);
        if (r == 0) {
            reinterpret_cast<float4*>(out)[q] = box;
            out[4 * Ns + q] = confm;
        } else {
            out[5 * Ns + q]  = 0.0f;
            out[22 * Ns + q] = mf;
        }
    }
}

extern "C" void kernel_launch(void* const* d_in, const int* in_sizes, int n_in,
                              void* d_out, int out_size)
{
    const float*  in     = (const float*)d_in[0];
    const float*  thr    = (const float*)d_in[1];
    const float4* priors = (const float4*)d_in[2];
    const float*  var    = (const float*)d_in[3];
    float* out = (float*)d_out;

    int N = in_sizes[2] / 4;   // priors is [N,4]

    int blocks = (N + 63) / 64;            // 64 priors per block (N=1e6 -> 15625)
    retina_decode_kernel<<<blocks, 128>>>(in, priors, thr, var, out, N);
}